// round 12
// baseline (speedup 1.0000x reference)
#include <cuda_runtime.h>
#include <cuda_bf16.h>
#include <cuda_fp16.h>
#include <math.h>
#include <stdint.h>

#define N_MAX 50000
#define NPAD  50048            // multiple of 128
#define E_MAX 800000
#define IN_F 256
#define FTOT 256   // NHEAD*OUT_F
#define NHEAD 4
#define OUT_F 64
#define ALPHA 0.2f

// ---------------- scratch (static device globals; no allocation) -------------
__device__ __half g_hb[(size_t)N_MAX * FTOT];    // projected features (fp16)
// chunk-tiled, PRE-SWIZZLED operand layouts: [chunk 0..3][row][128 bytes]
__device__ __nv_bfloat16 g_xAhi[(size_t)4 * NPAD * 64];
__device__ __nv_bfloat16 g_xAlo[(size_t)4 * NPAD * 64];
__device__ __nv_bfloat16 g_WBhi[4 * 256 * 64];
__device__ __nv_bfloat16 g_WBlo[4 * 256 * 64];
__device__ float g_hl[N_MAX * NHEAD];
__device__ float g_hr[N_MAX * NHEAD];
__device__ int   g_deg[N_MAX];
__device__ int   g_incl[N_MAX];
__device__ int   g_blockSums[64];
__device__ int   g_blockOff[64];
__device__ int   g_offs[N_MAX + 1];
__device__ int   g_cursor[N_MAX];
__device__ int   g_col_sorted[E_MAX];

// ---------------- helpers ------------------------------------------------------
static __device__ __forceinline__ uint32_t s2u(const void* p) {
    return (uint32_t)__cvta_generic_to_shared(p);
}

#define SMEM_SWIZZLE_128B(off) ((off) ^ (((off) >> 3) & 0x70))

#define LDSM_X4(r0, r1, r2, r3, addr) \
    asm volatile("ldmatrix.sync.aligned.m8n8.x4.shared.b16 {%0,%1,%2,%3}, [%4];" \
        : "=r"(r0), "=r"(r1), "=r"(r2), "=r"(r3) : "r"(addr))

static __device__ __forceinline__ void mma_bf16(
    float* c, uint32_t a0, uint32_t a1, uint32_t a2, uint32_t a3,
    uint32_t b0, uint32_t b1)
{
    asm volatile(
        "mma.sync.aligned.m16n8k16.row.col.f32.bf16.bf16.f32 "
        "{%0,%1,%2,%3}, {%4,%5,%6,%7}, {%8,%9}, {%0,%1,%2,%3};"
        : "+f"(c[0]), "+f"(c[1]), "+f"(c[2]), "+f"(c[3])
        : "r"(a0), "r"(a1), "r"(a2), "r"(a3), "r"(b0), "r"(b1));
}

#define MBARRIER_INIT(mbar, count) \
    asm volatile("mbarrier.init.shared.b64 [%0], %1;" \
        :: "r"((uint32_t)(mbar)), "r"((uint32_t)(count)) : "memory")
#define MBARRIER_EXPECT_TX(mbar, bytes) \
    asm volatile("mbarrier.arrive.expect_tx.shared.b64 _, [%0], %1;" \
        :: "r"((uint32_t)(mbar)), "r"((uint32_t)(bytes)) : "memory")
#define CP_ASYNC_BULK(dst, src, bytes, mbar) \
    asm volatile("cp.async.bulk.shared::cluster.global.mbarrier::complete_tx::bytes [%0], [%1], %2, [%3];" \
        :: "r"((uint32_t)(dst)), "l"(src), "r"((uint32_t)(bytes)), "r"((uint32_t)(mbar)) : "memory")

#define MBARRIER_WAIT_PARITY(mbar_smem_addr, phase_parity) do { \
    uint32_t _mbar = (uint32_t)(mbar_smem_addr); \
    uint32_t _parity = (uint32_t)(phase_parity); \
    uint32_t _done; \
    asm volatile( \
        "{\n\t.reg .pred p;\n\t" \
        "mbarrier.try_wait.parity.acquire.cta.shared::cta.b64 p, [%1], %2;\n\t" \
        "selp.b32 %0, 1, 0, p;\n\t}" \
        : "=r"(_done) : "r"(_mbar), "r"(_parity) : "memory"); \
    if (!_done) { \
        asm volatile( \
            "{\n\t.reg .pred P1;\n\t" \
            "WAIT_LOOP_%=:\n\t" \
            "mbarrier.try_wait.parity.acquire.cta.shared::cta.b64 P1, [%0], %1, 0x989680;\n\t" \
            "@P1 bra.uni WAIT_DONE_%=;\n\t" \
            "bra.uni WAIT_LOOP_%=;\n\t" \
            "WAIT_DONE_%=:\n\t}" \
            :: "r"(_mbar), "r"(_parity) : "memory"); \
    } \
} while(0)

// ---------------- split kernels (write chunk-tiled, pre-swizzled layouts) -----
__global__ __launch_bounds__(256) void split_x_kernel(const float* __restrict__ x, int total4)
{
    int i = blockIdx.x * blockDim.x + threadIdx.x;
    if (i >= total4) return;
    float4 v = ((const float4*)x)[i];
    int r  = i >> 6;            // row
    int kq = (i & 63) * 4;      // k start (multiple of 4)
    int c  = kq >> 6;           // chunk 0..3
    int b  = (kq & 63) * 2;     // byte within 128B row (multiple of 8)
    uint32_t sb = (uint32_t)b ^ (uint32_t)((r & 7) * 16);   // pre-swizzle
    size_t off = ((size_t)c * NPAD + (size_t)r) * 128 + sb;

    __nv_bfloat16 h0 = __float2bfloat16(v.x);
    __nv_bfloat16 h1 = __float2bfloat16(v.y);
    __nv_bfloat16 h2 = __float2bfloat16(v.z);
    __nv_bfloat16 h3 = __float2bfloat16(v.w);
    __nv_bfloat16 l0 = __float2bfloat16(v.x - __bfloat162float(h0));
    __nv_bfloat16 l1 = __float2bfloat16(v.y - __bfloat162float(h1));
    __nv_bfloat16 l2 = __float2bfloat16(v.z - __bfloat162float(h2));
    __nv_bfloat16 l3 = __float2bfloat16(v.w - __bfloat162float(h3));

    uint32_t hA, hB, lA, lB;
    {
        __nv_bfloat162 t0 = __halves2bfloat162(h0, h1);
        __nv_bfloat162 t1 = __halves2bfloat162(h2, h3);
        __nv_bfloat162 u0 = __halves2bfloat162(l0, l1);
        __nv_bfloat162 u1 = __halves2bfloat162(l2, l3);
        hA = *(uint32_t*)&t0; hB = *(uint32_t*)&t1;
        lA = *(uint32_t*)&u0; lB = *(uint32_t*)&u1;
    }
    *(uint2*)((char*)g_xAhi + off) = make_uint2(hA, hB);
    *(uint2*)((char*)g_xAlo + off) = make_uint2(lA, lB);
}

__global__ __launch_bounds__(256) void split_W_kernel(const float* __restrict__ W)
{
    int idx = blockIdx.x * blockDim.x + threadIdx.x;   // 65536
    if (idx >= FTOT * IN_F) return;
    int n = idx >> 8;           // output col (B row)
    int k = idx & 255;
    float v = W[k * FTOT + n];
    __nv_bfloat16 hi = __float2bfloat16(v);
    __nv_bfloat16 lo = __float2bfloat16(v - __bfloat162float(hi));
    int c = k >> 6;
    uint32_t sb = (uint32_t)((k & 63) * 2) ^ (uint32_t)((n & 7) * 16);
    size_t off = ((size_t)c * 256 + (size_t)n) * 128 + sb;
    *(__nv_bfloat16*)((char*)g_WBhi + off) = hi;
    *(__nv_bfloat16*)((char*)g_WBlo + off) = lo;
}

__global__ void zero_hlr_kernel(int N) {
    int i = blockIdx.x * blockDim.x + threadIdx.x;
    if (i < N * NHEAD) { g_hl[i] = 0.f; g_hr[i] = 0.f; }
}

// ---------------- software-pipelined chunk compute ----------------------------
// Double-buffered a-frags (per ks) and b-frags (per p): every ldmatrix issues
// one step ahead of its consuming mma, hiding the 29-cyc LDS latency.
static __device__ __forceinline__ void compute_chunk(
    float acc[2][8][4], const uint32_t aAddr[2], const uint32_t bAddr[4],
    uint32_t bufofs)
{
    uint32_t aF[2][2][4];   // [parity][mt][frag]
    uint32_t bF[2][4];      // [parity][frag]

    LDSM_X4(aF[0][0][0], aF[0][0][1], aF[0][0][2], aF[0][0][3], aAddr[0] + bufofs);
    LDSM_X4(aF[0][1][0], aF[0][1][1], aF[0][1][2], aF[0][1][3], aAddr[1] + bufofs);
    LDSM_X4(bF[0][0], bF[0][1], bF[0][2], bF[0][3], bAddr[0] + bufofs);

#pragma unroll
    for (int ks = 0; ks < 4; ks++) {
        const int kp = ks & 1, kn = kp ^ 1;
        if (ks < 3) {
            LDSM_X4(aF[kn][0][0], aF[kn][0][1], aF[kn][0][2], aF[kn][0][3],
                    (aAddr[0] + bufofs) ^ (uint32_t)((ks + 1) * 32));
            LDSM_X4(aF[kn][1][0], aF[kn][1][1], aF[kn][1][2], aF[kn][1][3],
                    (aAddr[1] + bufofs) ^ (uint32_t)((ks + 1) * 32));
        }
#pragma unroll
        for (int p = 0; p < 4; p++) {
            const int bp = p & 1, bn = bp ^ 1;
            if (p < 3) {
                LDSM_X4(bF[bn][0], bF[bn][1], bF[bn][2], bF[bn][3],
                        (bAddr[p + 1] + bufofs) ^ (uint32_t)(ks * 32));
            } else if (ks < 3) {
                LDSM_X4(bF[bn][0], bF[bn][1], bF[bn][2], bF[bn][3],
                        (bAddr[0] + bufofs) ^ (uint32_t)((ks + 1) * 32));
            }
            mma_bf16(acc[0][2*p],     aF[kp][0][0], aF[kp][0][1], aF[kp][0][2], aF[kp][0][3],
                     bF[bp][0], bF[bp][1]);
            mma_bf16(acc[0][2*p + 1], aF[kp][0][0], aF[kp][0][1], aF[kp][0][2], aF[kp][0][3],
                     bF[bp][2], bF[bp][3]);
            mma_bf16(acc[1][2*p],     aF[kp][1][0], aF[kp][1][1], aF[kp][1][2], aF[kp][1][3],
                     bF[bp][0], bF[bp][1]);
            mma_bf16(acc[1][2*p + 1], aF[kp][1][0], aF[kp][1][1], aF[kp][1][2], aF[kp][1][3],
                     bF[bp][2], bF[bp][3]);
        }
    }
}

// ---------------- bulk-copy warp-MMA split-bf16 GEMM (3-stage pipeline) -------
// CTA 128x128; 8 warps 2(N) x 4(M); warp tile 32(M) x 64(N).
// Virtual K = 768 = 12 chunks of 64: c 0-3 hi*hi, 4-7 lo*hi, 8-11 hi*lo.
__global__ __launch_bounds__(256, 2) void gemm_mma_kernel(
    int Mrows, const float* __restrict__ a_l, const float* __restrict__ a_r)
{
    extern __shared__ char smem[];   // [3 x (A16K|B16K)][mbars]
    uint64_t* mbars = (uint64_t*)(smem + 98304);
    const int tid = threadIdx.x;
    const int wid = tid >> 5;
    const int lane = tid & 31;
    const int warp_m = wid & 3;
    const int warp_n = wid >> 2;
    const int mBase = blockIdx.x * 128;
    const int nBase = blockIdx.y * 128;

    float acc[2][8][4];
#pragma unroll
    for (int mt = 0; mt < 2; mt++)
#pragma unroll
        for (int nt = 0; nt < 8; nt++)
#pragma unroll
            for (int q = 0; q < 4; q++) acc[mt][nt][q] = 0.f;

    // hoisted swizzled ldmatrix bases (stage 0); stage s = +s*32768
    uint32_t aAddr[2], bAddr[4];
#pragma unroll
    for (int mt = 0; mt < 2; mt++) {
        uint32_t off = (uint32_t)(warp_m * 32 + mt * 16 + (lane & 15)) * 128
                     + (lane >> 4) * 16;
        aAddr[mt] = s2u(smem + SMEM_SWIZZLE_128B(off));
    }
#pragma unroll
    for (int p = 0; p < 4; p++) {
        uint32_t row = (uint32_t)(warp_n * 64 + p * 16 + (lane & 7) + ((lane >> 4) << 3));
        uint32_t off = row * 128 + (((lane >> 3) & 1) << 4);
        bAddr[p] = s2u(smem + 16384 + SMEM_SWIZZLE_128B(off));
    }

    if (tid == 0) {
        MBARRIER_INIT(s2u(&mbars[0]), 1);
        MBARRIER_INIT(s2u(&mbars[1]), 1);
        MBARRIER_INIT(s2u(&mbars[2]), 1);
    }
    __syncthreads();

#define ISSUE_BULK(c, buf) do {                                                   \
        const char* Ab = ((c) >= 4 && (c) < 8) ? (const char*)g_xAlo              \
                                               : (const char*)g_xAhi;             \
        const char* Bb = ((c) < 8) ? (const char*)g_WBhi : (const char*)g_WBlo;   \
        const char* srcA = Ab + ((size_t)((c) & 3) * NPAD + (size_t)mBase) * 128; \
        const char* srcB = Bb + ((size_t)((c) & 3) * 256 + (size_t)nBase) * 128;  \
        uint32_t mb = s2u(&mbars[buf]);                                           \
        MBARRIER_EXPECT_TX(mb, 32768u);                                           \
        CP_ASYNC_BULK(s2u(smem + (buf) * 32768), srcA, 16384u, mb);               \
        CP_ASYNC_BULK(s2u(smem + (buf) * 32768 + 16384), srcB, 16384u, mb);       \
    } while (0)

    if (tid == 0) {
        ISSUE_BULK(0, 0);
        ISSUE_BULK(1, 1);
        ISSUE_BULK(2, 2);
    }

#pragma unroll
    for (int c = 0; c < 12; c++) {
        const int buf = c % 3;
        MBARRIER_WAIT_PARITY(s2u(&mbars[buf]), (uint32_t)((c / 3) & 1));
        compute_chunk(acc, aAddr, bAddr, (uint32_t)(buf * 32768));
        __syncthreads();                    // all warps done reading buf
        if (c + 3 < 12 && tid == 0) ISSUE_BULK(c + 3, buf);
    }

    // epilogue: write fp16 h + fused hl/hr partial reduction (fp32)
    const int tg = lane >> 2;
    const int tl = lane & 3;
    const int head = blockIdx.y * 2 + warp_n;
#pragma unroll
    for (int mt = 0; mt < 2; mt++) {
        int r0 = mBase + warp_m * 32 + mt * 16 + tg;
        int r1 = r0 + 8;
        float pl0 = 0.f, pr0 = 0.f, pl1 = 0.f, pr1 = 0.f;
#pragma unroll
        for (int nt = 0; nt < 8; nt++) {
            int col = nBase + warp_n * 64 + nt * 8 + 2 * tl;
            if (r0 < Mrows) {
                __half2 hp2 = __floats2half2_rn(acc[mt][nt][0], acc[mt][nt][1]);
                *(__half2*)(g_hb + (size_t)r0 * FTOT + col) = hp2;
            }
            if (r1 < Mrows) {
                __half2 hp2 = __floats2half2_rn(acc[mt][nt][2], acc[mt][nt][3]);
                *(__half2*)(g_hb + (size_t)r1 * FTOT + col) = hp2;
            }
            float2 alv = *(const float2*)(a_l + col);
            float2 arv = *(const float2*)(a_r + col);
            pl0 += alv.x * acc[mt][nt][0] + alv.y * acc[mt][nt][1];
            pr0 += arv.x * acc[mt][nt][0] + arv.y * acc[mt][nt][1];
            pl1 += alv.x * acc[mt][nt][2] + alv.y * acc[mt][nt][3];
            pr1 += arv.x * acc[mt][nt][2] + arv.y * acc[mt][nt][3];
        }
#pragma unroll
        for (int off = 1; off <= 2; off <<= 1) {
            pl0 += __shfl_xor_sync(0xffffffffu, pl0, off, 4);
            pr0 += __shfl_xor_sync(0xffffffffu, pr0, off, 4);
            pl1 += __shfl_xor_sync(0xffffffffu, pl1, off, 4);
            pr1 += __shfl_xor_sync(0xffffffffu, pr1, off, 4);
        }
        if (tl == 0) {
            if (r0 < Mrows) {
                atomicAdd(&g_hl[r0 * NHEAD + head], pl0);
                atomicAdd(&g_hr[r0 * NHEAD + head], pr0);
            }
            if (r1 < Mrows) {
                atomicAdd(&g_hl[r1 * NHEAD + head], pl1);
                atomicAdd(&g_hr[r1 * NHEAD + head], pr1);
            }
        }
    }
#undef ISSUE_BULK
}

// -------------- CSR build ----------------------------------------------------
__global__ void zero_deg_kernel(int N) {
    int i = blockIdx.x * blockDim.x + threadIdx.x;
    if (i < N) g_deg[i] = 0;
}

__global__ void hist_kernel(const int* __restrict__ edge, int E) {
    int i = blockIdx.x * blockDim.x + threadIdx.x;
    if (i < E) atomicAdd(&g_deg[edge[i]], 1);
}

__global__ __launch_bounds__(1024) void scan_block_kernel(int N) {
    __shared__ int s[1024];
    int i = blockIdx.x * 1024 + threadIdx.x;
    int v = (i < N) ? g_deg[i] : 0;
    s[threadIdx.x] = v;
    __syncthreads();
#pragma unroll
    for (int off = 1; off < 1024; off <<= 1) {
        int t = (threadIdx.x >= off) ? s[threadIdx.x - off] : 0;
        __syncthreads();
        s[threadIdx.x] += t;
        __syncthreads();
    }
    if (i < N) g_incl[i] = s[threadIdx.x];
    if (threadIdx.x == 1023) g_blockSums[blockIdx.x] = s[1023];
}

__global__ void scan_sums_kernel(int nb) {
    if (threadIdx.x == 0) {
        int run = 0;
        for (int b = 0; b < nb; b++) {
            g_blockOff[b] = run;
            run += g_blockSums[b];
        }
    }
}

__global__ __launch_bounds__(1024) void finalize_kernel(int N) {
    int i = blockIdx.x * blockDim.x + threadIdx.x;
    if (i < N) {
        int F = g_incl[i] + g_blockOff[i >> 10];
        g_offs[i + 1] = F;
        g_cursor[i] = F - g_deg[i];
    }
    if (i == 0) g_offs[0] = 0;
}

__global__ void scatter_kernel(const int* __restrict__ edge, int E) {
    int i = blockIdx.x * blockDim.x + threadIdx.x;
    if (i < E) {
        int r = edge[i];
        int c = edge[E + i];
        int p = atomicAdd(&g_cursor[r], 1);
        g_col_sorted[p] = c;
    }
}

// -------------- SINGLE-PASS segment softmax + SpMM (warp per node) -----------
// out[r] = sum_j w_j h[c_j] / sum_j w_j  with unnormalized w_j = exp(lrelu(..)).
static __device__ __forceinline__ float lrelu(float v) {
    return v > 0.f ? v : ALPHA * v;
}

static __device__ __forceinline__ void acc8_fp16(
    float* a, uint4 q, float w)
{
    float2 f0 = __half22float2(*(__half2*)&q.x);
    float2 f1 = __half22float2(*(__half2*)&q.y);
    float2 f2 = __half22float2(*(__half2*)&q.z);
    float2 f3 = __half22float2(*(__half2*)&q.w);
    a[0] = fmaf(w, f0.x, a[0]); a[1] = fmaf(w, f0.y, a[1]);
    a[2] = fmaf(w, f1.x, a[2]); a[3] = fmaf(w, f1.y, a[3]);
    a[4] = fmaf(w, f2.x, a[4]); a[5] = fmaf(w, f2.y, a[5]);
    a[6] = fmaf(w, f3.x, a[6]); a[7] = fmaf(w, f3.y, a[7]);
}

__global__ __launch_bounds__(256) void aggregate_kernel(float* __restrict__ out, int N) {
    int warp = (blockIdx.x * blockDim.x + threadIdx.x) >> 5;
    if (warp >= N) return;
    int lane = threadIdx.x & 31;
    int head = lane >> 3;

    int s = g_offs[warp];
    int e = g_offs[warp + 1];
    float hln = g_hl[warp * NHEAD + head];

    float a[8] = {0.f, 0.f, 0.f, 0.f, 0.f, 0.f, 0.f, 0.f};
    float wsum = 0.f;
    const int chan = lane * 8;
    const __half* hbase = g_hb + chan;

    int j = s;
    int jend4 = s + ((e - s) & ~3);
    // col indices prefetched one group ahead to break the L2-latency chain
    int c0, c1, c2, c3;
    if (j < jend4) {
        c0 = g_col_sorted[j];     c1 = g_col_sorted[j + 1];
        c2 = g_col_sorted[j + 2]; c3 = g_col_sorted[j + 3];
    }
    for (; j < jend4; j += 4) {
        int n0, n1, n2, n3;
        if (j + 4 < jend4) {
            n0 = g_col_sorted[j + 4]; n1 = g_col_sorted[j + 5];
            n2 = g_col_sorted[j + 6]; n3 = g_col_sorted[j + 7];
        }
        float w0 = __expf(lrelu(hln + g_hr[c0 * NHEAD + head]));
        float w1 = __expf(lrelu(hln + g_hr[c1 * NHEAD + head]));
        float w2 = __expf(lrelu(hln + g_hr[c2 * NHEAD + head]));
        float w3 = __expf(lrelu(hln + g_hr[c3 * NHEAD + head]));
        uint4 q0 = *(const uint4*)(hbase + (size_t)c0 * FTOT);
        uint4 q1 = *(const uint4*)(hbase + (size_t)c1 * FTOT);
        uint4 q2 = *(const uint4*)(hbase + (size_t)c2 * FTOT);
        uint4 q3 = *(const uint4*)(hbase + (size_t)c3 * FTOT);
        wsum += (w0 + w1) + (w2 + w3);
        acc8_fp16(a, q0, w0);
        acc8_fp16(a, q1, w1);
        acc8_fp16(a, q2, w2);
        acc8_fp16(a, q3, w3);
        c0 = n0; c1 = n1; c2 = n2; c3 = n3;
    }
    for (; j < e; j++) {
        int c = g_col_sorted[j];
        float w = __expf(lrelu(hln + g_hr[c * NHEAD + head]));
        uint4 q = *(const uint4*)(hbase + (size_t)c * FTOT);
        wsum += w;
        acc8_fp16(a, q, w);
    }
    float inv = (e > s) ? 1.0f / wsum : 0.f;
#pragma unroll
    for (int i = 0; i < 8; i++) a[i] *= inv;

    float* op = out + (size_t)warp * FTOT + chan;
    *(float4*)op       = make_float4(a[0], a[1], a[2], a[3]);
    *(float4*)(op + 4) = make_float4(a[4], a[5], a[6], a[7]);
}

// -------------- launch --------------------------------------------------------
extern "C" void kernel_launch(void* const* d_in, const int* in_sizes, int n_in,
                              void* d_out, int out_size)
{
    const float* x    = (const float*)d_in[0];
    const int*   edge = (const int*)  d_in[1];
    const float* W    = (const float*)d_in[2];
    const float* a_l  = (const float*)d_in[3];
    const float* a_r  = (const float*)d_in[4];
    float* out = (float*)d_out;

    int N = in_sizes[0] / IN_F;
    int E = in_sizes[1] / 2;

    static cudaStream_t s_csr = nullptr;
    static cudaEvent_t ev_fork = nullptr, ev_join = nullptr;
    if (s_csr == nullptr) {
        cudaStreamCreateWithFlags(&s_csr, cudaStreamNonBlocking);
        cudaEventCreateWithFlags(&ev_fork, cudaEventDisableTiming);
        cudaEventCreateWithFlags(&ev_join, cudaEventDisableTiming);
        cudaFuncSetAttribute(gemm_mma_kernel,
                             cudaFuncAttributeMaxDynamicSharedMemorySize, 98304 + 256);
    }

    // fork for the CSR side stream
    cudaEventRecord(ev_fork, 0);
    cudaStreamWaitEvent(s_csr, ev_fork, 0);

    // main chain first (gemm is kernel launch #4 -> profiled by ncu -s/-c)
    int total4 = (N * IN_F) / 4;
    zero_hlr_kernel<<<(N * NHEAD + 255) / 256, 256>>>(N);
    split_x_kernel<<<(total4 + 255) / 256, 256>>>(x, total4);
    split_W_kernel<<<(FTOT * IN_F + 255) / 256, 256>>>(W);
    dim3 ggrid((N + 127) / 128, FTOT / 128);
    gemm_mma_kernel<<<ggrid, 256, 98304 + 256>>>(N, a_l, a_r);

    // CSR build on side stream (concurrent with main chain)
    zero_deg_kernel<<<(N + 255) / 256, 256, 0, s_csr>>>(N);
    hist_kernel<<<(E + 255) / 256, 256, 0, s_csr>>>(edge, E);
    int nb = (N + 1023) / 1024;
    scan_block_kernel<<<nb, 1024, 0, s_csr>>>(N);
    scan_sums_kernel<<<1, 32, 0, s_csr>>>(nb);
    finalize_kernel<<<nb, 1024, 0, s_csr>>>(N);
    scatter_kernel<<<(E + 255) / 256, 256, 0, s_csr>>>(edge, E);
    cudaEventRecord(ev_join, s_csr);

    // join, then single-pass softmax + aggregation
    cudaStreamWaitEvent(0, ev_join, 0);
    aggregate_kernel<<<(N * 32 + 255) / 256, 256>>>(out, N);
}

// round 13
// speedup vs baseline: 1.1329x; 1.1329x over previous
#include <cuda_runtime.h>
#include <cuda_bf16.h>
#include <cuda_fp16.h>
#include <math.h>
#include <stdint.h>

#define N_MAX 50000
#define NPAD  50048            // multiple of 128
#define E_MAX 800000
#define IN_F 256
#define FTOT 256   // NHEAD*OUT_F
#define NHEAD 4
#define OUT_F 64
#define ALPHA 0.2f

// ---------------- scratch (static device globals; no allocation) -------------
__device__ __half g_hb[(size_t)N_MAX * FTOT];    // projected features (fp16)
// chunk-tiled, PRE-SWIZZLED operand layouts: [chunk 0..3][row][128 bytes]
__device__ __half g_xAhi[(size_t)4 * NPAD * 64];
__device__ __half g_xAlo[(size_t)4 * NPAD * 64];
__device__ __half g_WB[4 * 256 * 64];            // W^T fp16 (single copy)
__device__ float g_hl[N_MAX * NHEAD];
__device__ float g_hr[N_MAX * NHEAD];
__device__ int   g_deg[N_MAX];
__device__ int   g_incl[N_MAX];
__device__ int   g_blockSums[64];
__device__ int   g_blockOff[64];
__device__ int   g_offs[N_MAX + 1];
__device__ int   g_cursor[N_MAX];
__device__ int   g_col_sorted[E_MAX];

// ---------------- helpers ------------------------------------------------------
static __device__ __forceinline__ uint32_t s2u(const void* p) {
    return (uint32_t)__cvta_generic_to_shared(p);
}

#define SMEM_SWIZZLE_128B(off) ((off) ^ (((off) >> 3) & 0x70))

#define LDSM_X4(r0, r1, r2, r3, addr) \
    asm volatile("ldmatrix.sync.aligned.m8n8.x4.shared.b16 {%0,%1,%2,%3}, [%4];" \
        : "=r"(r0), "=r"(r1), "=r"(r2), "=r"(r3) : "r"(addr))

static __device__ __forceinline__ void mma_fp16(
    float* c, uint32_t a0, uint32_t a1, uint32_t a2, uint32_t a3,
    uint32_t b0, uint32_t b1)
{
    asm volatile(
        "mma.sync.aligned.m16n8k16.row.col.f32.f16.f16.f32 "
        "{%0,%1,%2,%3}, {%4,%5,%6,%7}, {%8,%9}, {%0,%1,%2,%3};"
        : "+f"(c[0]), "+f"(c[1]), "+f"(c[2]), "+f"(c[3])
        : "r"(a0), "r"(a1), "r"(a2), "r"(a3), "r"(b0), "r"(b1));
}

#define MBARRIER_INIT(mbar, count) \
    asm volatile("mbarrier.init.shared.b64 [%0], %1;" \
        :: "r"((uint32_t)(mbar)), "r"((uint32_t)(count)) : "memory")
#define MBARRIER_EXPECT_TX(mbar, bytes) \
    asm volatile("mbarrier.arrive.expect_tx.shared.b64 _, [%0], %1;" \
        :: "r"((uint32_t)(mbar)), "r"((uint32_t)(bytes)) : "memory")
#define CP_ASYNC_BULK(dst, src, bytes, mbar) \
    asm volatile("cp.async.bulk.shared::cluster.global.mbarrier::complete_tx::bytes [%0], [%1], %2, [%3];" \
        :: "r"((uint32_t)(dst)), "l"(src), "r"((uint32_t)(bytes)), "r"((uint32_t)(mbar)) : "memory")

#define MBARRIER_WAIT_PARITY(mbar_smem_addr, phase_parity) do { \
    uint32_t _mbar = (uint32_t)(mbar_smem_addr); \
    uint32_t _parity = (uint32_t)(phase_parity); \
    uint32_t _done; \
    asm volatile( \
        "{\n\t.reg .pred p;\n\t" \
        "mbarrier.try_wait.parity.acquire.cta.shared::cta.b64 p, [%1], %2;\n\t" \
        "selp.b32 %0, 1, 0, p;\n\t}" \
        : "=r"(_done) : "r"(_mbar), "r"(_parity) : "memory"); \
    if (!_done) { \
        asm volatile( \
            "{\n\t.reg .pred P1;\n\t" \
            "WAIT_LOOP_%=:\n\t" \
            "mbarrier.try_wait.parity.acquire.cta.shared::cta.b64 P1, [%0], %1, 0x989680;\n\t" \
            "@P1 bra.uni WAIT_DONE_%=;\n\t" \
            "bra.uni WAIT_LOOP_%=;\n\t" \
            "WAIT_DONE_%=:\n\t}" \
            :: "r"(_mbar), "r"(_parity) : "memory"); \
    } \
} while(0)

// ---------------- split kernels (write chunk-tiled, pre-swizzled layouts) -----
__global__ __launch_bounds__(256) void split_x_kernel(const float* __restrict__ x, int total4)
{
    int i = blockIdx.x * blockDim.x + threadIdx.x;
    if (i >= total4) return;
    float4 v = ((const float4*)x)[i];
    int r  = i >> 6;            // row
    int kq = (i & 63) * 4;      // k start (multiple of 4)
    int c  = kq >> 6;           // chunk 0..3
    int b  = (kq & 63) * 2;     // byte within 128B row (multiple of 8)
    uint32_t sb = (uint32_t)b ^ (uint32_t)((r & 7) * 16);   // pre-swizzle
    size_t off = ((size_t)c * NPAD + (size_t)r) * 128 + sb;

    __half h0 = __float2half(v.x);
    __half h1 = __float2half(v.y);
    __half h2 = __float2half(v.z);
    __half h3 = __float2half(v.w);
    __half l0 = __float2half(v.x - __half2float(h0));
    __half l1 = __float2half(v.y - __half2float(h1));
    __half l2 = __float2half(v.z - __half2float(h2));
    __half l3 = __float2half(v.w - __half2float(h3));

    __half2 t0 = __halves2half2(h0, h1);
    __half2 t1 = __halves2half2(h2, h3);
    __half2 u0 = __halves2half2(l0, l1);
    __half2 u1 = __halves2half2(l2, l3);
    *(uint2*)((char*)g_xAhi + off) = make_uint2(*(uint32_t*)&t0, *(uint32_t*)&t1);
    *(uint2*)((char*)g_xAlo + off) = make_uint2(*(uint32_t*)&u0, *(uint32_t*)&u1);
}

__global__ __launch_bounds__(256) void split_W_kernel(const float* __restrict__ W)
{
    int idx = blockIdx.x * blockDim.x + threadIdx.x;   // 65536
    if (idx >= FTOT * IN_F) return;
    int n = idx >> 8;           // output col (B row)
    int k = idx & 255;
    float v = W[k * FTOT + n];
    int c = k >> 6;
    uint32_t sb = (uint32_t)((k & 63) * 2) ^ (uint32_t)((n & 7) * 16);
    size_t off = ((size_t)c * 256 + (size_t)n) * 128 + sb;
    *(__half*)((char*)g_WB + off) = __float2half(v);
}

__global__ void zero_hlr_kernel(int N) {
    int i = blockIdx.x * blockDim.x + threadIdx.x;
    if (i < N * NHEAD) { g_hl[i] = 0.f; g_hr[i] = 0.f; }
}

// ---------------- bulk-copy warp-MMA split-fp16 GEMM (3-stage pipeline) -------
// CTA 128x128; 8 warps 2(N) x 4(M); warp tile 32(M) x 64(N).
// Virtual K = 512 = 8 chunks of 64: c 0-3 A_hi*B, c 4-7 A_lo*B.
__global__ __launch_bounds__(256, 2) void gemm_mma_kernel(
    int Mrows, const float* __restrict__ a_l, const float* __restrict__ a_r)
{
    extern __shared__ char smem[];   // [3 x (A16K|B16K)][mbars]
    uint64_t* mbars = (uint64_t*)(smem + 98304);
    const int tid = threadIdx.x;
    const int wid = tid >> 5;
    const int lane = tid & 31;
    const int warp_m = wid & 3;
    const int warp_n = wid >> 2;
    const int mBase = blockIdx.x * 128;
    const int nBase = blockIdx.y * 128;

    float acc[2][8][4];
#pragma unroll
    for (int mt = 0; mt < 2; mt++)
#pragma unroll
        for (int nt = 0; nt < 8; nt++)
#pragma unroll
            for (int q = 0; q < 4; q++) acc[mt][nt][q] = 0.f;

    // hoisted swizzled ldmatrix bases (stage 0); stage s = +s*32768
    uint32_t aAddr[2], bAddr[4];
#pragma unroll
    for (int mt = 0; mt < 2; mt++) {
        uint32_t off = (uint32_t)(warp_m * 32 + mt * 16 + (lane & 15)) * 128
                     + (lane >> 4) * 16;
        aAddr[mt] = s2u(smem + SMEM_SWIZZLE_128B(off));
    }
#pragma unroll
    for (int p = 0; p < 4; p++) {
        uint32_t row = (uint32_t)(warp_n * 64 + p * 16 + (lane & 7) + ((lane >> 4) << 3));
        uint32_t off = row * 128 + (((lane >> 3) & 1) << 4);
        bAddr[p] = s2u(smem + 16384 + SMEM_SWIZZLE_128B(off));
    }

    if (tid == 0) {
        MBARRIER_INIT(s2u(&mbars[0]), 1);
        MBARRIER_INIT(s2u(&mbars[1]), 1);
        MBARRIER_INIT(s2u(&mbars[2]), 1);
    }
    __syncthreads();

#define ISSUE_BULK(c, buf) do {                                                   \
        const char* Ab = ((c) >= 4) ? (const char*)g_xAlo : (const char*)g_xAhi;  \
        const char* srcA = Ab + ((size_t)((c) & 3) * NPAD + (size_t)mBase) * 128; \
        const char* srcB = (const char*)g_WB                                      \
                         + ((size_t)((c) & 3) * 256 + (size_t)nBase) * 128;       \
        uint32_t mb = s2u(&mbars[buf]);                                           \
        MBARRIER_EXPECT_TX(mb, 32768u);                                           \
        CP_ASYNC_BULK(s2u(smem + (buf) * 32768), srcA, 16384u, mb);               \
        CP_ASYNC_BULK(s2u(smem + (buf) * 32768 + 16384), srcB, 16384u, mb);       \
    } while (0)

#define COMPUTE_CHUNK(BUFOFS) do {                                            \
        _Pragma("unroll")                                                     \
        for (int ks = 0; ks < 4; ks++) {                                      \
            uint32_t a0_, a1_, a2_, a3_, a4_, a5_, a6_, a7_;                  \
            LDSM_X4(a0_, a1_, a2_, a3_, (aAddr[0] + (BUFOFS)) ^ (uint32_t)(ks * 32)); \
            LDSM_X4(a4_, a5_, a6_, a7_, (aAddr[1] + (BUFOFS)) ^ (uint32_t)(ks * 32)); \
            _Pragma("unroll")                                                 \
            for (int p = 0; p < 4; p++) {                                     \
                uint32_t b0_, b1_, b2_, b3_;                                  \
                LDSM_X4(b0_, b1_, b2_, b3_, (bAddr[p] + (BUFOFS)) ^ (uint32_t)(ks * 32)); \
                mma_fp16(acc[0][2*p],     a0_, a1_, a2_, a3_, b0_, b1_);      \
                mma_fp16(acc[0][2*p + 1], a0_, a1_, a2_, a3_, b2_, b3_);      \
                mma_fp16(acc[1][2*p],     a4_, a5_, a6_, a7_, b0_, b1_);      \
                mma_fp16(acc[1][2*p + 1], a4_, a5_, a6_, a7_, b2_, b3_);      \
            }                                                                 \
        }                                                                     \
    } while (0)

    if (tid == 0) {
        ISSUE_BULK(0, 0);
        ISSUE_BULK(1, 1);
        ISSUE_BULK(2, 2);
    }

#pragma unroll
    for (int c = 0; c < 8; c++) {
        const int buf = c % 3;
        MBARRIER_WAIT_PARITY(s2u(&mbars[buf]), (uint32_t)((c / 3) & 1));
        COMPUTE_CHUNK((uint32_t)(buf * 32768));
        __syncthreads();                    // all warps done reading buf
        if (c + 3 < 8 && tid == 0) ISSUE_BULK(c + 3, buf);
    }

    // epilogue: write fp16 h + fused hl/hr partial reduction (fp32)
    const int tg = lane >> 2;
    const int tl = lane & 3;
    const int head = blockIdx.y * 2 + warp_n;
#pragma unroll
    for (int mt = 0; mt < 2; mt++) {
        int r0 = mBase + warp_m * 32 + mt * 16 + tg;
        int r1 = r0 + 8;
        float pl0 = 0.f, pr0 = 0.f, pl1 = 0.f, pr1 = 0.f;
#pragma unroll
        for (int nt = 0; nt < 8; nt++) {
            int col = nBase + warp_n * 64 + nt * 8 + 2 * tl;
            if (r0 < Mrows) {
                __half2 hp2 = __floats2half2_rn(acc[mt][nt][0], acc[mt][nt][1]);
                *(__half2*)(g_hb + (size_t)r0 * FTOT + col) = hp2;
            }
            if (r1 < Mrows) {
                __half2 hp2 = __floats2half2_rn(acc[mt][nt][2], acc[mt][nt][3]);
                *(__half2*)(g_hb + (size_t)r1 * FTOT + col) = hp2;
            }
            float2 alv = *(const float2*)(a_l + col);
            float2 arv = *(const float2*)(a_r + col);
            pl0 += alv.x * acc[mt][nt][0] + alv.y * acc[mt][nt][1];
            pr0 += arv.x * acc[mt][nt][0] + arv.y * acc[mt][nt][1];
            pl1 += alv.x * acc[mt][nt][2] + alv.y * acc[mt][nt][3];
            pr1 += arv.x * acc[mt][nt][2] + arv.y * acc[mt][nt][3];
        }
#pragma unroll
        for (int off = 1; off <= 2; off <<= 1) {
            pl0 += __shfl_xor_sync(0xffffffffu, pl0, off, 4);
            pr0 += __shfl_xor_sync(0xffffffffu, pr0, off, 4);
            pl1 += __shfl_xor_sync(0xffffffffu, pl1, off, 4);
            pr1 += __shfl_xor_sync(0xffffffffu, pr1, off, 4);
        }
        if (tl == 0) {
            if (r0 < Mrows) {
                atomicAdd(&g_hl[r0 * NHEAD + head], pl0);
                atomicAdd(&g_hr[r0 * NHEAD + head], pr0);
            }
            if (r1 < Mrows) {
                atomicAdd(&g_hl[r1 * NHEAD + head], pl1);
                atomicAdd(&g_hr[r1 * NHEAD + head], pr1);
            }
        }
    }
#undef ISSUE_BULK
#undef COMPUTE_CHUNK
}

// -------------- CSR build ----------------------------------------------------
__global__ void zero_deg_kernel(int N) {
    int i = blockIdx.x * blockDim.x + threadIdx.x;
    if (i < N) g_deg[i] = 0;
}

__global__ void hist_kernel(const int* __restrict__ edge, int E) {
    int i = blockIdx.x * blockDim.x + threadIdx.x;
    if (i < E) atomicAdd(&g_deg[edge[i]], 1);
}

__global__ __launch_bounds__(1024) void scan_block_kernel(int N) {
    __shared__ int s[1024];
    int i = blockIdx.x * 1024 + threadIdx.x;
    int v = (i < N) ? g_deg[i] : 0;
    s[threadIdx.x] = v;
    __syncthreads();
#pragma unroll
    for (int off = 1; off < 1024; off <<= 1) {
        int t = (threadIdx.x >= off) ? s[threadIdx.x - off] : 0;
        __syncthreads();
        s[threadIdx.x] += t;
        __syncthreads();
    }
    if (i < N) g_incl[i] = s[threadIdx.x];
    if (threadIdx.x == 1023) g_blockSums[blockIdx.x] = s[1023];
}

__global__ void scan_sums_kernel(int nb) {
    if (threadIdx.x == 0) {
        int run = 0;
        for (int b = 0; b < nb; b++) {
            g_blockOff[b] = run;
            run += g_blockSums[b];
        }
    }
}

__global__ __launch_bounds__(1024) void finalize_kernel(int N) {
    int i = blockIdx.x * blockDim.x + threadIdx.x;
    if (i < N) {
        int F = g_incl[i] + g_blockOff[i >> 10];
        g_offs[i + 1] = F;
        g_cursor[i] = F - g_deg[i];
    }
    if (i == 0) g_offs[0] = 0;
}

__global__ void scatter_kernel(const int* __restrict__ edge, int E) {
    int i = blockIdx.x * blockDim.x + threadIdx.x;
    if (i < E) {
        int r = edge[i];
        int c = edge[E + i];
        int p = atomicAdd(&g_cursor[r], 1);
        g_col_sorted[p] = c;
    }
}

// -------------- SINGLE-PASS segment softmax + SpMM (warp per node) -----------
// out[r] = sum_j w_j h[c_j] / sum_j w_j  with unnormalized w_j = exp(lrelu(..)).
static __device__ __forceinline__ float lrelu(float v) {
    return v > 0.f ? v : ALPHA * v;
}

static __device__ __forceinline__ void acc8_fp16(
    float* a, uint4 q, float w)
{
    float2 f0 = __half22float2(*(__half2*)&q.x);
    float2 f1 = __half22float2(*(__half2*)&q.y);
    float2 f2 = __half22float2(*(__half2*)&q.z);
    float2 f3 = __half22float2(*(__half2*)&q.w);
    a[0] = fmaf(w, f0.x, a[0]); a[1] = fmaf(w, f0.y, a[1]);
    a[2] = fmaf(w, f1.x, a[2]); a[3] = fmaf(w, f1.y, a[3]);
    a[4] = fmaf(w, f2.x, a[4]); a[5] = fmaf(w, f2.y, a[5]);
    a[6] = fmaf(w, f3.x, a[6]); a[7] = fmaf(w, f3.y, a[7]);
}

__global__ __launch_bounds__(256) void aggregate_kernel(float* __restrict__ out, int N) {
    int warp = (blockIdx.x * blockDim.x + threadIdx.x) >> 5;
    if (warp >= N) return;
    int lane = threadIdx.x & 31;
    int head = lane >> 3;

    int s = g_offs[warp];
    int e = g_offs[warp + 1];
    float hln = g_hl[warp * NHEAD + head];

    float a[8] = {0.f, 0.f, 0.f, 0.f, 0.f, 0.f, 0.f, 0.f};
    float wsum = 0.f;
    const int chan = lane * 8;
    const __half* hbase = g_hb + chan;

    int j = s;
    int jend4 = s + ((e - s) & ~3);
    for (; j < jend4; j += 4) {
        int c0 = g_col_sorted[j];
        int c1 = g_col_sorted[j + 1];
        int c2 = g_col_sorted[j + 2];
        int c3 = g_col_sorted[j + 3];
        float w0 = __expf(lrelu(hln + g_hr[c0 * NHEAD + head]));
        float w1 = __expf(lrelu(hln + g_hr[c1 * NHEAD + head]));
        float w2 = __expf(lrelu(hln + g_hr[c2 * NHEAD + head]));
        float w3 = __expf(lrelu(hln + g_hr[c3 * NHEAD + head]));
        uint4 q0 = *(const uint4*)(hbase + (size_t)c0 * FTOT);
        uint4 q1 = *(const uint4*)(hbase + (size_t)c1 * FTOT);
        uint4 q2 = *(const uint4*)(hbase + (size_t)c2 * FTOT);
        uint4 q3 = *(const uint4*)(hbase + (size_t)c3 * FTOT);
        wsum += (w0 + w1) + (w2 + w3);
        acc8_fp16(a, q0, w0);
        acc8_fp16(a, q1, w1);
        acc8_fp16(a, q2, w2);
        acc8_fp16(a, q3, w3);
    }
    for (; j < e; j++) {
        int c = g_col_sorted[j];
        float w = __expf(lrelu(hln + g_hr[c * NHEAD + head]));
        uint4 q = *(const uint4*)(hbase + (size_t)c * FTOT);
        wsum += w;
        acc8_fp16(a, q, w);
    }
    float inv = (e > s) ? 1.0f / wsum : 0.f;
#pragma unroll
    for (int i = 0; i < 8; i++) a[i] *= inv;

    float* op = out + (size_t)warp * FTOT + chan;
    *(float4*)op       = make_float4(a[0], a[1], a[2], a[3]);
    *(float4*)(op + 4) = make_float4(a[4], a[5], a[6], a[7]);
}

// -------------- launch --------------------------------------------------------
extern "C" void kernel_launch(void* const* d_in, const int* in_sizes, int n_in,
                              void* d_out, int out_size)
{
    const float* x    = (const float*)d_in[0];
    const int*   edge = (const int*)  d_in[1];
    const float* W    = (const float*)d_in[2];
    const float* a_l  = (const float*)d_in[3];
    const float* a_r  = (const float*)d_in[4];
    float* out = (float*)d_out;

    int N = in_sizes[0] / IN_F;
    int E = in_sizes[1] / 2;

    static cudaStream_t s_csr = nullptr;
    static cudaEvent_t ev_fork = nullptr, ev_join = nullptr;
    if (s_csr == nullptr) {
        cudaStreamCreateWithFlags(&s_csr, cudaStreamNonBlocking);
        cudaEventCreateWithFlags(&ev_fork, cudaEventDisableTiming);
        cudaEventCreateWithFlags(&ev_join, cudaEventDisableTiming);
        cudaFuncSetAttribute(gemm_mma_kernel,
                             cudaFuncAttributeMaxDynamicSharedMemorySize, 98304 + 256);
    }

    // fork for the CSR side stream
    cudaEventRecord(ev_fork, 0);
    cudaStreamWaitEvent(s_csr, ev_fork, 0);

    // main chain first (gemm is kernel launch #4 -> profiled by ncu -s/-c)
    int total4 = (N * IN_F) / 4;
    zero_hlr_kernel<<<(N * NHEAD + 255) / 256, 256>>>(N);
    split_x_kernel<<<(total4 + 255) / 256, 256>>>(x, total4);
    split_W_kernel<<<(FTOT * IN_F + 255) / 256, 256>>>(W);
    dim3 ggrid((N + 127) / 128, FTOT / 128);
    gemm_mma_kernel<<<ggrid, 256, 98304 + 256>>>(N, a_l, a_r);

    // CSR build on side stream (concurrent with main chain)
    zero_deg_kernel<<<(N + 255) / 256, 256, 0, s_csr>>>(N);
    hist_kernel<<<(E + 255) / 256, 256, 0, s_csr>>>(edge, E);
    int nb = (N + 1023) / 1024;
    scan_block_kernel<<<nb, 1024, 0, s_csr>>>(N);
    scan_sums_kernel<<<1, 32, 0, s_csr>>>(nb);
    finalize_kernel<<<nb, 1024, 0, s_csr>>>(N);
    scatter_kernel<<<(E + 255) / 256, 256, 0, s_csr>>>(edge, E);
    cudaEventRecord(ev_join, s_csr);

    // join, then single-pass softmax + aggregation
    cudaStreamWaitEvent(0, ev_join, 0);
    aggregate_kernel<<<(N * 32 + 255) / 256, 256>>>(out, N);
}

// round 15
// speedup vs baseline: 1.2562x; 1.1088x over previous
#include <cuda_runtime.h>
#include <cuda_bf16.h>
#include <cuda_fp16.h>
#include <math.h>
#include <stdint.h>

#define N_MAX 50000
#define NPAD  50048            // multiple of 128
#define E_MAX 800000
#define IN_F 256
#define FTOT 256   // NHEAD*OUT_F
#define NHEAD 4
#define OUT_F 64
#define ALPHA 0.2f

// ---------------- scratch (static device globals; no allocation) -------------
__device__ __half g_hb[(size_t)N_MAX * FTOT];    // projected features (fp16)
// chunk-tiled, PRE-SWIZZLED operand layouts: [chunk 0..3][row][128 bytes]
__device__ __half g_xA[(size_t)4 * NPAD * 64];   // x fp16 (single copy)
__device__ __half g_WB[4 * 256 * 64];            // W^T fp16 (single copy)
__device__ float g_hl[N_MAX * NHEAD];
__device__ float g_hr[N_MAX * NHEAD];
__device__ int   g_deg[N_MAX];
__device__ int   g_incl[N_MAX];
__device__ int   g_blockSums[64];
__device__ int   g_blockOff[64];
__device__ int   g_offs[N_MAX + 1];
__device__ int   g_cursor[N_MAX];
__device__ int   g_col_sorted[E_MAX];

// ---------------- helpers ------------------------------------------------------
static __device__ __forceinline__ uint32_t s2u(const void* p) {
    return (uint32_t)__cvta_generic_to_shared(p);
}

#define SMEM_SWIZZLE_128B(off) ((off) ^ (((off) >> 3) & 0x70))

#define LDSM_X4(r0, r1, r2, r3, addr) \
    asm volatile("ldmatrix.sync.aligned.m8n8.x4.shared.b16 {%0,%1,%2,%3}, [%4];" \
        : "=r"(r0), "=r"(r1), "=r"(r2), "=r"(r3) : "r"(addr))

static __device__ __forceinline__ void mma_fp16(
    float* c, uint32_t a0, uint32_t a1, uint32_t a2, uint32_t a3,
    uint32_t b0, uint32_t b1)
{
    asm volatile(
        "mma.sync.aligned.m16n8k16.row.col.f32.f16.f16.f32 "
        "{%0,%1,%2,%3}, {%4,%5,%6,%7}, {%8,%9}, {%0,%1,%2,%3};"
        : "+f"(c[0]), "+f"(c[1]), "+f"(c[2]), "+f"(c[3])
        : "r"(a0), "r"(a1), "r"(a2), "r"(a3), "r"(b0), "r"(b1));
}

#define MBARRIER_INIT(mbar, count) \
    asm volatile("mbarrier.init.shared.b64 [%0], %1;" \
        :: "r"((uint32_t)(mbar)), "r"((uint32_t)(count)) : "memory")
#define MBARRIER_EXPECT_TX(mbar, bytes) \
    asm volatile("mbarrier.arrive.expect_tx.shared.b64 _, [%0], %1;" \
        :: "r"((uint32_t)(mbar)), "r"((uint32_t)(bytes)) : "memory")
#define CP_ASYNC_BULK(dst, src, bytes, mbar) \
    asm volatile("cp.async.bulk.shared::cluster.global.mbarrier::complete_tx::bytes [%0], [%1], %2, [%3];" \
        :: "r"((uint32_t)(dst)), "l"(src), "r"((uint32_t)(bytes)), "r"((uint32_t)(mbar)) : "memory")

#define MBARRIER_WAIT_PARITY(mbar_smem_addr, phase_parity) do { \
    uint32_t _mbar = (uint32_t)(mbar_smem_addr); \
    uint32_t _parity = (uint32_t)(phase_parity); \
    uint32_t _done; \
    asm volatile( \
        "{\n\t.reg .pred p;\n\t" \
        "mbarrier.try_wait.parity.acquire.cta.shared::cta.b64 p, [%1], %2;\n\t" \
        "selp.b32 %0, 1, 0, p;\n\t}" \
        : "=r"(_done) : "r"(_mbar), "r"(_parity) : "memory"); \
    if (!_done) { \
        asm volatile( \
            "{\n\t.reg .pred P1;\n\t" \
            "WAIT_LOOP_%=:\n\t" \
            "mbarrier.try_wait.parity.acquire.cta.shared::cta.b64 P1, [%0], %1, 0x989680;\n\t" \
            "@P1 bra.uni WAIT_DONE_%=;\n\t" \
            "bra.uni WAIT_LOOP_%=;\n\t" \
            "WAIT_DONE_%=:\n\t}" \
            :: "r"(_mbar), "r"(_parity) : "memory"); \
    } \
} while(0)

// ---------------- split kernels (write chunk-tiled, pre-swizzled layouts) -----
__global__ __launch_bounds__(256) void split_x_kernel(const float* __restrict__ x, int total4)
{
    int i = blockIdx.x * blockDim.x + threadIdx.x;
    if (i >= total4) return;
    float4 v = ((const float4*)x)[i];
    int r  = i >> 6;            // row
    int kq = (i & 63) * 4;      // k start (multiple of 4)
    int c  = kq >> 6;           // chunk 0..3
    int b  = (kq & 63) * 2;     // byte within 128B row (multiple of 8)
    uint32_t sb = (uint32_t)b ^ (uint32_t)((r & 7) * 16);   // pre-swizzle
    size_t off = ((size_t)c * NPAD + (size_t)r) * 128 + sb;

    __half2 t0 = __floats2half2_rn(v.x, v.y);
    __half2 t1 = __floats2half2_rn(v.z, v.w);
    *(uint2*)((char*)g_xA + off) = make_uint2(*(uint32_t*)&t0, *(uint32_t*)&t1);
}

__global__ __launch_bounds__(256) void split_W_kernel(const float* __restrict__ W)
{
    int idx = blockIdx.x * blockDim.x + threadIdx.x;   // 65536
    if (idx >= FTOT * IN_F) return;
    int n = idx >> 8;           // output col (B row)
    int k = idx & 255;
    float v = W[k * FTOT + n];
    int c = k >> 6;
    uint32_t sb = (uint32_t)((k & 63) * 2) ^ (uint32_t)((n & 7) * 16);
    size_t off = ((size_t)c * 256 + (size_t)n) * 128 + sb;
    *(__half*)((char*)g_WB + off) = __float2half(v);
}

__global__ void zero_hlr_kernel(int N) {
    int i = blockIdx.x * blockDim.x + threadIdx.x;
    if (i < N * NHEAD) { g_hl[i] = 0.f; g_hr[i] = 0.f; }
}

// ---------------- bulk-copy warp-MMA fp16 GEMM (3-stage pipeline) -------------
// CTA 128x128; 8 warps 2(N) x 4(M); warp tile 32(M) x 64(N).
// K = 256 = 4 chunks of 64.
__global__ __launch_bounds__(256, 2) void gemm_mma_kernel(
    int Mrows, const float* __restrict__ a_l, const float* __restrict__ a_r)
{
    extern __shared__ char smem[];   // [3 x (A16K|B16K)][mbars]
    uint64_t* mbars = (uint64_t*)(smem + 98304);
    const int tid = threadIdx.x;
    const int wid = tid >> 5;
    const int lane = tid & 31;
    const int warp_m = wid & 3;
    const int warp_n = wid >> 2;
    const int mBase = blockIdx.x * 128;
    const int nBase = blockIdx.y * 128;

    float acc[2][8][4];
#pragma unroll
    for (int mt = 0; mt < 2; mt++)
#pragma unroll
        for (int nt = 0; nt < 8; nt++)
#pragma unroll
            for (int q = 0; q < 4; q++) acc[mt][nt][q] = 0.f;

    // hoisted swizzled ldmatrix bases (stage 0); stage s = +s*32768
    uint32_t aAddr[2], bAddr[4];
#pragma unroll
    for (int mt = 0; mt < 2; mt++) {
        uint32_t off = (uint32_t)(warp_m * 32 + mt * 16 + (lane & 15)) * 128
                     + (lane >> 4) * 16;
        aAddr[mt] = s2u(smem + SMEM_SWIZZLE_128B(off));
    }
#pragma unroll
    for (int p = 0; p < 4; p++) {
        uint32_t row = (uint32_t)(warp_n * 64 + p * 16 + (lane & 7) + ((lane >> 4) << 3));
        uint32_t off = row * 128 + (((lane >> 3) & 1) << 4);
        bAddr[p] = s2u(smem + 16384 + SMEM_SWIZZLE_128B(off));
    }

    if (tid == 0) {
        MBARRIER_INIT(s2u(&mbars[0]), 1);
        MBARRIER_INIT(s2u(&mbars[1]), 1);
        MBARRIER_INIT(s2u(&mbars[2]), 1);
    }
    __syncthreads();

#define ISSUE_BULK(c, buf) do {                                                   \
        const char* srcA = (const char*)g_xA                                      \
                         + ((size_t)(c) * NPAD + (size_t)mBase) * 128;            \
        const char* srcB = (const char*)g_WB                                      \
                         + ((size_t)(c) * 256 + (size_t)nBase) * 128;             \
        uint32_t mb = s2u(&mbars[buf]);                                           \
        MBARRIER_EXPECT_TX(mb, 32768u);                                           \
        CP_ASYNC_BULK(s2u(smem + (buf) * 32768), srcA, 16384u, mb);               \
        CP_ASYNC_BULK(s2u(smem + (buf) * 32768 + 16384), srcB, 16384u, mb);       \
    } while (0)

#define COMPUTE_CHUNK(BUFOFS) do {                                            \
        _Pragma("unroll")                                                     \
        for (int ks = 0; ks < 4; ks++) {                                      \
            uint32_t a0_, a1_, a2_, a3_, a4_, a5_, a6_, a7_;                  \
            LDSM_X4(a0_, a1_, a2_, a3_, (aAddr[0] + (BUFOFS)) ^ (uint32_t)(ks * 32)); \
            LDSM_X4(a4_, a5_, a6_, a7_, (aAddr[1] + (BUFOFS)) ^ (uint32_t)(ks * 32)); \
            _Pragma("unroll")                                                 \
            for (int p = 0; p < 4; p++) {                                     \
                uint32_t b0_, b1_, b2_, b3_;                                  \
                LDSM_X4(b0_, b1_, b2_, b3_, (bAddr[p] + (BUFOFS)) ^ (uint32_t)(ks * 32)); \
                mma_fp16(acc[0][2*p],     a0_, a1_, a2_, a3_, b0_, b1_);      \
                mma_fp16(acc[0][2*p + 1], a0_, a1_, a2_, a3_, b2_, b3_);      \
                mma_fp16(acc[1][2*p],     a4_, a5_, a6_, a7_, b0_, b1_);      \
                mma_fp16(acc[1][2*p + 1], a4_, a5_, a6_, a7_, b2_, b3_);      \
            }                                                                 \
        }                                                                     \
    } while (0)

    if (tid == 0) {
        ISSUE_BULK(0, 0);
        ISSUE_BULK(1, 1);
        ISSUE_BULK(2, 2);
    }

#pragma unroll
    for (int c = 0; c < 4; c++) {
        const int buf = c % 3;
        MBARRIER_WAIT_PARITY(s2u(&mbars[buf]), (uint32_t)((c / 3) & 1));
        COMPUTE_CHUNK((uint32_t)(buf * 32768));
        __syncthreads();                    // all warps done reading buf
        if (c + 3 < 4 && tid == 0) ISSUE_BULK(c + 3, buf);
    }

    // epilogue: write fp16 h + fused hl/hr partial reduction (fp32)
    const int tg = lane >> 2;
    const int tl = lane & 3;
    const int head = blockIdx.y * 2 + warp_n;
#pragma unroll
    for (int mt = 0; mt < 2; mt++) {
        int r0 = mBase + warp_m * 32 + mt * 16 + tg;
        int r1 = r0 + 8;
        float pl0 = 0.f, pr0 = 0.f, pl1 = 0.f, pr1 = 0.f;
#pragma unroll
        for (int nt = 0; nt < 8; nt++) {
            int col = nBase + warp_n * 64 + nt * 8 + 2 * tl;
            if (r0 < Mrows) {
                __half2 hp2 = __floats2half2_rn(acc[mt][nt][0], acc[mt][nt][1]);
                *(__half2*)(g_hb + (size_t)r0 * FTOT + col) = hp2;
            }
            if (r1 < Mrows) {
                __half2 hp2 = __floats2half2_rn(acc[mt][nt][2], acc[mt][nt][3]);
                *(__half2*)(g_hb + (size_t)r1 * FTOT + col) = hp2;
            }
            float2 alv = *(const float2*)(a_l + col);
            float2 arv = *(const float2*)(a_r + col);
            pl0 += alv.x * acc[mt][nt][0] + alv.y * acc[mt][nt][1];
            pr0 += arv.x * acc[mt][nt][0] + arv.y * acc[mt][nt][1];
            pl1 += alv.x * acc[mt][nt][2] + alv.y * acc[mt][nt][3];
            pr1 += arv.x * acc[mt][nt][2] + arv.y * acc[mt][nt][3];
        }
#pragma unroll
        for (int off = 1; off <= 2; off <<= 1) {
            pl0 += __shfl_xor_sync(0xffffffffu, pl0, off, 4);
            pr0 += __shfl_xor_sync(0xffffffffu, pr0, off, 4);
            pl1 += __shfl_xor_sync(0xffffffffu, pl1, off, 4);
            pr1 += __shfl_xor_sync(0xffffffffu, pr1, off, 4);
        }
        if (tl == 0) {
            if (r0 < Mrows) {
                atomicAdd(&g_hl[r0 * NHEAD + head], pl0);
                atomicAdd(&g_hr[r0 * NHEAD + head], pr0);
            }
            if (r1 < Mrows) {
                atomicAdd(&g_hl[r1 * NHEAD + head], pl1);
                atomicAdd(&g_hr[r1 * NHEAD + head], pr1);
            }
        }
    }
#undef ISSUE_BULK
#undef COMPUTE_CHUNK
}

// -------------- CSR build ----------------------------------------------------
__global__ void zero_deg_kernel(int N) {
    int i = blockIdx.x * blockDim.x + threadIdx.x;
    if (i < N) g_deg[i] = 0;
}

__global__ void hist_kernel(const int* __restrict__ edge, int E) {
    int i = blockIdx.x * blockDim.x + threadIdx.x;
    if (i < E) atomicAdd(&g_deg[edge[i]], 1);
}

__global__ __launch_bounds__(1024) void scan_block_kernel(int N) {
    __shared__ int s[1024];
    int i = blockIdx.x * 1024 + threadIdx.x;
    int v = (i < N) ? g_deg[i] : 0;
    s[threadIdx.x] = v;
    __syncthreads();
#pragma unroll
    for (int off = 1; off < 1024; off <<= 1) {
        int t = (threadIdx.x >= off) ? s[threadIdx.x - off] : 0;
        __syncthreads();
        s[threadIdx.x] += t;
        __syncthreads();
    }
    if (i < N) g_incl[i] = s[threadIdx.x];
    if (threadIdx.x == 1023) g_blockSums[blockIdx.x] = s[1023];
}

__global__ void scan_sums_kernel(int nb) {
    if (threadIdx.x == 0) {
        int run = 0;
        for (int b = 0; b < nb; b++) {
            g_blockOff[b] = run;
            run += g_blockSums[b];
        }
    }
}

__global__ __launch_bounds__(1024) void finalize_kernel(int N) {
    int i = blockIdx.x * blockDim.x + threadIdx.x;
    if (i < N) {
        int F = g_incl[i] + g_blockOff[i >> 10];
        g_offs[i + 1] = F;
        g_cursor[i] = F - g_deg[i];
    }
    if (i == 0) g_offs[0] = 0;
}

__global__ void scatter_kernel(const int* __restrict__ edge, int E) {
    int i = blockIdx.x * blockDim.x + threadIdx.x;
    if (i < E) {
        int r = edge[i];
        int c = edge[E + i];
        int p = atomicAdd(&g_cursor[r], 1);
        g_col_sorted[p] = c;
    }
}

// -------------- SINGLE-PASS segment softmax + SpMM (warp per node) -----------
// out[r] = sum_j w_j h[c_j] / sum_j w_j  with unnormalized w_j = exp(lrelu(..)).
static __device__ __forceinline__ float lrelu(float v) {
    return v > 0.f ? v : ALPHA * v;
}

static __device__ __forceinline__ void acc8_fp16(
    float* a, uint4 q, float w)
{
    float2 f0 = __half22float2(*(__half2*)&q.x);
    float2 f1 = __half22float2(*(__half2*)&q.y);
    float2 f2 = __half22float2(*(__half2*)&q.z);
    float2 f3 = __half22float2(*(__half2*)&q.w);
    a[0] = fmaf(w, f0.x, a[0]); a[1] = fmaf(w, f0.y, a[1]);
    a[2] = fmaf(w, f1.x, a[2]); a[3] = fmaf(w, f1.y, a[3]);
    a[4] = fmaf(w, f2.x, a[4]); a[5] = fmaf(w, f2.y, a[5]);
    a[6] = fmaf(w, f3.x, a[6]); a[7] = fmaf(w, f3.y, a[7]);
}

__global__ __launch_bounds__(256) void aggregate_kernel(float* __restrict__ out, int N) {
    int warp = (blockIdx.x * blockDim.x + threadIdx.x) >> 5;
    if (warp >= N) return;
    int lane = threadIdx.x & 31;
    int head = lane >> 3;

    int s = g_offs[warp];
    int e = g_offs[warp + 1];
    float hln = g_hl[warp * NHEAD + head];

    float a[8] = {0.f, 0.f, 0.f, 0.f, 0.f, 0.f, 0.f, 0.f};
    float wsum = 0.f;
    const int chan = lane * 8;
    const __half* hbase = g_hb + chan;

    int j = s;
    int jend4 = s + ((e - s) & ~3);
    for (; j < jend4; j += 4) {
        int c0 = g_col_sorted[j];
        int c1 = g_col_sorted[j + 1];
        int c2 = g_col_sorted[j + 2];
        int c3 = g_col_sorted[j + 3];
        float w0 = __expf(lrelu(hln + g_hr[c0 * NHEAD + head]));
        float w1 = __expf(lrelu(hln + g_hr[c1 * NHEAD + head]));
        float w2 = __expf(lrelu(hln + g_hr[c2 * NHEAD + head]));
        float w3 = __expf(lrelu(hln + g_hr[c3 * NHEAD + head]));
        uint4 q0 = *(const uint4*)(hbase + (size_t)c0 * FTOT);
        uint4 q1 = *(const uint4*)(hbase + (size_t)c1 * FTOT);
        uint4 q2 = *(const uint4*)(hbase + (size_t)c2 * FTOT);
        uint4 q3 = *(const uint4*)(hbase + (size_t)c3 * FTOT);
        wsum += (w0 + w1) + (w2 + w3);
        acc8_fp16(a, q0, w0);
        acc8_fp16(a, q1, w1);
        acc8_fp16(a, q2, w2);
        acc8_fp16(a, q3, w3);
    }
    for (; j < e; j++) {
        int c = g_col_sorted[j];
        float w = __expf(lrelu(hln + g_hr[c * NHEAD + head]));
        uint4 q = *(const uint4*)(hbase + (size_t)c * FTOT);
        wsum += w;
        acc8_fp16(a, q, w);
    }
    float inv = (e > s) ? 1.0f / wsum : 0.f;
#pragma unroll
    for (int i = 0; i < 8; i++) a[i] *= inv;

    float* op = out + (size_t)warp * FTOT + chan;
    *(float4*)op       = make_float4(a[0], a[1], a[2], a[3]);
    *(float4*)(op + 4) = make_float4(a[4], a[5], a[6], a[7]);
}

// -------------- launch --------------------------------------------------------
extern "C" void kernel_launch(void* const* d_in, const int* in_sizes, int n_in,
                              void* d_out, int out_size)
{
    const float* x    = (const float*)d_in[0];
    const int*   edge = (const int*)  d_in[1];
    const float* W    = (const float*)d_in[2];
    const float* a_l  = (const float*)d_in[3];
    const float* a_r  = (const float*)d_in[4];
    float* out = (float*)d_out;

    int N = in_sizes[0] / IN_F;
    int E = in_sizes[1] / 2;

    static cudaStream_t s_csr = nullptr;
    static cudaEvent_t ev_fork = nullptr, ev_join = nullptr;
    if (s_csr == nullptr) {
        cudaStreamCreateWithFlags(&s_csr, cudaStreamNonBlocking);
        cudaEventCreateWithFlags(&ev_fork, cudaEventDisableTiming);
        cudaEventCreateWithFlags(&ev_join, cudaEventDisableTiming);
        cudaFuncSetAttribute(gemm_mma_kernel,
                             cudaFuncAttributeMaxDynamicSharedMemorySize, 98304 + 256);
    }

    // fork for the CSR side stream
    cudaEventRecord(ev_fork, 0);
    cudaStreamWaitEvent(s_csr, ev_fork, 0);

    // main chain first (gemm is kernel launch #4 -> profiled by ncu -s/-c)
    int total4 = (N * IN_F) / 4;
    zero_hlr_kernel<<<(N * NHEAD + 255) / 256, 256>>>(N);
    split_x_kernel<<<(total4 + 255) / 256, 256>>>(x, total4);
    split_W_kernel<<<(FTOT * IN_F + 255) / 256, 256>>>(W);
    dim3 ggrid((N + 127) / 128, FTOT / 128);
    gemm_mma_kernel<<<ggrid, 256, 98304 + 256>>>(N, a_l, a_r);

    // CSR build on side stream (concurrent with main chain)
    zero_deg_kernel<<<(N + 255) / 256, 256, 0, s_csr>>>(N);
    hist_kernel<<<(E + 255) / 256, 256, 0, s_csr>>>(edge, E);
    int nb = (N + 1023) / 1024;
    scan_block_kernel<<<nb, 1024, 0, s_csr>>>(N);
    scan_sums_kernel<<<1, 32, 0, s_csr>>>(nb);
    finalize_kernel<<<nb, 1024, 0, s_csr>>>(N);
    scatter_kernel<<<(E + 255) / 256, 256, 0, s_csr>>>(edge, E);
    cudaEventRecord(ev_join, s_csr);

    // join, then single-pass softmax + aggregation
    cudaStreamWaitEvent(0, ev_join, 0);
    aggregate_kernel<<<(N * 32 + 255) / 256, 256>>>(out, N);
}